// round 2
// baseline (speedup 1.0000x reference)
#include <cuda_runtime.h>
#include <cuda_bf16.h>

#define EDIM 64
#define FHh 96
#define FWw 320
#define NPIX (FHh*FWw)

// img_feat transposed to [pixel][channel] (channel-contiguous)
__device__ float g_imgT[NPIX * EDIM];

typedef unsigned long long ull;

static __device__ __forceinline__ ull pk2(float x, float y) {
    ull r; asm("mov.b64 %0,{%1,%2};" : "=l"(r) : "f"(x), "f"(y)); return r;
}
static __device__ __forceinline__ float2 upk2(ull v) {
    float2 r; asm("mov.b64 {%0,%1},%2;" : "=f"(r.x), "=f"(r.y) : "l"(v)); return r;
}
static __device__ __forceinline__ void fma2(ull &d, ull a, ull b) {
    asm("fma.rn.f32x2 %0,%1,%2,%0;" : "+l"(d) : "l"(a), "l"(b));
}

// ------------------- transpose img_feat (E, H*W) -> (H*W, E) -------------------
__global__ void transpose_kernel(const float* __restrict__ src) {
    __shared__ float t[32][33];
    int p0 = blockIdx.x * 32;   // pixel tile (960)
    int e0 = blockIdx.y * 32;   // channel tile (2)
    int tx = threadIdx.x, ty = threadIdx.y;  // (32, 8)
    #pragma unroll
    for (int r = 0; r < 32; r += 8)
        t[ty + r][tx] = src[(size_t)(e0 + ty + r) * NPIX + p0 + tx];
    __syncthreads();
    #pragma unroll
    for (int r = 0; r < 32; r += 8)
        g_imgT[(size_t)(p0 + ty + r) * EDIM + e0 + tx] = t[tx][ty + r];
}

// ------------------- bilinear corner gather (16 channels / lane) -------------------
static __device__ __forceinline__ void gatherCorner(int cx, int cy, float wgt,
                                                    ull f[8], int c) {
    if ((unsigned)cx < (unsigned)FWw && (unsigned)cy < (unsigned)FHh) {
        const ulonglong2* p =
            (const ulonglong2*)&g_imgT[(size_t)(cy * FWw + cx) * EDIM + c * 16];
        ull w2 = pk2(wgt, wgt);
        #pragma unroll
        for (int r = 0; r < 4; r++) {
            ulonglong2 q = p[r];
            fma2(f[2*r],   w2, q.x);
            fma2(f[2*r+1], w2, q.y);
        }
    }
}

// ------------------- main fused kernel -------------------
// Warp = one z-column (8 voxels). lane = v*4 + c, v=z in 0..7, c=channel-quarter.
// Each lane holds bev channels [c*16, c*16+16) of voxel v in registers across all
// 3 iterations. Block = 8 warps = 8 consecutive x at fixed y.
__global__ __launch_bounds__(256) void bev_kernel(
    const float* __restrict__ velo,  const float* __restrict__ intr,
    const float* __restrict__ bev_emb,
    const float* __restrict__ Woff,  const float* __restrict__ boff,
    const float* __restrict__ soff,  const float* __restrict__ Ww,
    const float* __restrict__ bw,    const float* __restrict__ Wl,
    const float* __restrict__ bl,    const float* __restrict__ lng,
    const float* __restrict__ lnb,   float* __restrict__ out)
{
    // W_l: row stride 80 floats, channel-chunk c at +c*20 floats (bank-skewed)
    __shared__ float s_wl[64 * 80];
    // 9-col GEMV weights (6 off + 3 w), row stride 12 + 8-float pad per 16 rows
    __shared__ float s_w9[64 * 12 + 24];
    __shared__ float s_bo[8], s_bw[4], s_bl[64], s_g[64], s_b[64];
    __shared__ float s_obuf[512];

    int tid  = threadIdx.x;
    int w    = tid >> 5, lane = tid & 31;
    int v    = lane >> 2, c = lane & 3;
    int y    = blockIdx.x >> 4;
    int xg   = blockIdx.x & 15;
    int x    = xg * 8 + w;

    // T = intrinsic @ T_velo2cam  (3x4)
    float T[12];
    #pragma unroll
    for (int r = 0; r < 3; r++)
        #pragma unroll
        for (int cc = 0; cc < 4; cc++)
            T[r*4+cc] = intr[r*3+0]*velo[0*4+cc] + intr[r*3+1]*velo[1*4+cc]
                      + intr[r*3+2]*velo[2*4+cc];

    float hx = 0.8f * (float)x;
    float hy = 51.2f - 0.8f * (float)y;
    float hz = 0.5f * (float)v - 2.5f;
    float p0 = T[0]*hx + T[1]*hy + T[2]*hz  + T[3];
    float p1 = T[4]*hx + T[5]*hy + T[6]*hz  + T[7];
    float p2 = T[8]*hx + T[9]*hy + T[10]*hz + T[11];
    float coordx = (p0 / p2) * (1.0f/640.0f) - 1.0f;
    float coordy = (p1 / p2) * (1.0f/192.0f) - 1.0f;

    // load bev (registers for whole kernel)
    int vox = x * 1024 + y * 8 + v;
    float bv[16];
    {
        const float4* bp = (const float4*)(bev_emb + (size_t)vox * 64 + c * 16);
        #pragma unroll
        for (int r = 0; r < 4; r++) {
            float4 q = bp[r];
            bv[4*r] = q.x; bv[4*r+1] = q.y; bv[4*r+2] = q.z; bv[4*r+3] = q.w;
        }
    }

    for (int it = 0; it < 3; ++it) {
        __syncthreads();
        // ---- cooperative weight staging ----
        for (int idx = tid; idx < 4096; idx += 256) {
            int e = idx >> 6, j = idx & 63;
            s_wl[e * 80 + (j >> 4) * 20 + (j & 15)] = Wl[it * 4096 + idx];
        }
        float sc = soff[it];
        for (int idx = tid; idx < 768; idx += 256) {
            int e = idx / 12, j = idx - e * 12;
            float val = 0.f;
            if (j < 6)       val = Woff[it * 384 + e * 6 + j];
            else if (j < 9)  val = Ww[it * 192 + e * 3 + (j - 6)];
            s_w9[e * 12 + (e >> 4) * 8 + j] = val;
        }
        if (tid < 6)                    s_bo[tid]      = boff[it*6 + tid] * sc;
        if (tid >= 32  && tid < 35)     s_bw[tid-32]   = bw[it*3 + tid-32];
        if (tid >= 64  && tid < 128)    s_bl[tid-64]   = bl[it*64 + tid-64];
        if (tid >= 128 && tid < 192)    s_g[tid-128]   = lng[it*64 + tid-128];
        if (tid >= 192)                 s_b[tid-192]   = lnb[it*64 + tid-192];
        __syncthreads();

        // ---- 9-output GEMV (offsets + attention logits) ----
        ull a0 = 0, a1 = 0, a2 = 0, a3 = 0; float a8 = 0.f;
        #pragma unroll
        for (int i = 0; i < 16; i++) {
            int e = c * 16 + i;
            float be = bv[i];
            ull be2 = pk2(be, be);
            const float* row = &s_w9[e * 12 + (e >> 4) * 8];
            ulonglong2 q0 = *(const ulonglong2*)row;
            ulonglong2 q1 = *(const ulonglong2*)(row + 4);
            fma2(a0, be2, q0.x); fma2(a1, be2, q0.y);
            fma2(a2, be2, q1.x); fma2(a3, be2, q1.y);
            a8 = fmaf(be, row[8], a8);
        }
        float d[9];
        { float2 t0 = upk2(a0); d[0]=t0.x; d[1]=t0.y;
          float2 t1 = upk2(a1); d[2]=t1.x; d[3]=t1.y;
          float2 t2 = upk2(a2); d[4]=t2.x; d[5]=t2.y;
          float2 t3 = upk2(a3); d[6]=t3.x; d[7]=t3.y; d[8]=a8; }
        #pragma unroll
        for (int s = 1; s <= 2; s <<= 1)
            #pragma unroll
            for (int t = 0; t < 9; t++)
                d[t] += __shfl_xor_sync(0xffffffffu, d[t], s);

        // ---- softmax over K=3 ----
        float l0 = d[6] + s_bw[0], l1 = d[7] + s_bw[1], l2 = d[8] + s_bw[2];
        float m  = fmaxf(l0, fmaxf(l1, l2));
        float e0 = __expf(l0 - m), e1 = __expf(l1 - m), e2 = __expf(l2 - m);
        float inv = 1.0f / (e0 + e1 + e2);
        float wk0 = e0 * inv, wk1 = e1 * inv, wk2 = e2 * inv;

        // ---- weighted bilinear gather (K=3 points, 4 corners each) ----
        ull f[8] = {0,0,0,0,0,0,0,0};
        float wks[3] = {wk0, wk1, wk2};
        #pragma unroll
        for (int k = 0; k < 3; k++) {
            float gx = coordx + d[2*k]   * sc + s_bo[2*k];
            float gy = coordy + d[2*k+1] * sc + s_bo[2*k+1];
            float fx = fmaf(gx, 160.f, 159.5f);   // ((gx+1)*320 - 1)/2
            float fy = fmaf(gy, 48.f,  47.5f);    // ((gy+1)*96  - 1)/2
            float x0f = floorf(fx), y0f = floorf(fy);
            int ix = (int)x0f, iy = (int)y0f;
            float wx1 = fx - x0f, wy1 = fy - y0f;
            float wx0 = 1.f - wx1, wy0 = 1.f - wy1;
            float wgt = wks[k];
            gatherCorner(ix,   iy,   wx0*wy0*wgt, f, c);
            gatherCorner(ix+1, iy,   wx1*wy0*wgt, f, c);
            gatherCorner(ix,   iy+1, wx0*wy1*wgt, f, c);
            gatherCorner(ix+1, iy+1, wx1*wy1*wgt, f, c);
        }
        #pragma unroll
        for (int r = 0; r < 8; r++) {
            float2 t = upk2(f[r]); bv[2*r] += t.x; bv[2*r+1] += t.y;
        }

        // ---- 64x64 matmul: h = bev @ W_l + b_l ----
        ull acc[8];
        #pragma unroll
        for (int r = 0; r < 8; r++)
            acc[r] = pk2(s_bl[c*16 + 2*r], s_bl[c*16 + 2*r + 1]);
        #pragma unroll
        for (int g = 0; g < 4; ++g) {
            int src = (lane & ~3) | g;      // lane holding e-chunk g of voxel v
            float ch[16];
            #pragma unroll
            for (int i = 0; i < 16; i++)
                ch[i] = __shfl_sync(0xffffffffu, bv[i], src);
            #pragma unroll
            for (int i = 0; i < 16; i++) {
                ull be2 = pk2(ch[i], ch[i]);
                const ulonglong2* wr =
                    (const ulonglong2*)&s_wl[(g*16 + i) * 80 + c * 20];
                ulonglong2 q0 = wr[0], q1 = wr[1], q2 = wr[2], q3 = wr[3];
                fma2(acc[0], be2, q0.x); fma2(acc[1], be2, q0.y);
                fma2(acc[2], be2, q1.x); fma2(acc[3], be2, q1.y);
                fma2(acc[4], be2, q2.x); fma2(acc[5], be2, q2.y);
                fma2(acc[6], be2, q3.x); fma2(acc[7], be2, q3.y);
            }
        }

        // ---- LayerNorm + residual ----
        float h[16];
        #pragma unroll
        for (int r = 0; r < 8; r++) {
            float2 t = upk2(acc[r]); h[2*r] = t.x; h[2*r+1] = t.y;
        }
        float s1 = 0.f, s2 = 0.f;
        #pragma unroll
        for (int i = 0; i < 16; i++) { s1 += h[i]; s2 += h[i]*h[i]; }
        #pragma unroll
        for (int s = 1; s <= 2; s <<= 1) {
            s1 += __shfl_xor_sync(0xffffffffu, s1, s);
            s2 += __shfl_xor_sync(0xffffffffu, s2, s);
        }
        float mu  = s1 * (1.f/64.f);
        float var = s2 * (1.f/64.f) - mu * mu;
        float rs  = rsqrtf(var + 1e-5f);
        #pragma unroll
        for (int i = 0; i < 16; i++)
            bv[i] += (h[i] - mu) * rs * s_g[c*16 + i] + s_b[c*16 + i];
    }

    // ---- mean over z (butterfly across v) + coalesced store ----
    #pragma unroll
    for (int i = 0; i < 16; i++) {
        float s = bv[i];
        s += __shfl_xor_sync(0xffffffffu, s, 4);
        s += __shfl_xor_sync(0xffffffffu, s, 8);
        s += __shfl_xor_sync(0xffffffffu, s, 16);
        bv[i] = s;
    }
    if (v == 0) {
        #pragma unroll
        for (int i = 0; i < 16; i++)
            s_obuf[(c*16 + i) * 8 + w] = bv[i] * 0.125f;
    }
    __syncthreads();
    for (int idx = tid; idx < 512; idx += 256) {
        int e = idx >> 3, xi = idx & 7;
        out[(size_t)e * 16384 + y * 128 + xg * 8 + xi] = s_obuf[idx];
    }
}

extern "C" void kernel_launch(void* const* d_in, const int* in_sizes, int n_in,
                              void* d_out, int out_size) {
    const float* velo = (const float*)d_in[0];
    const float* intr = (const float*)d_in[1];
    const float* img  = (const float*)d_in[2];
    const float* bev  = (const float*)d_in[3];
    const float* Woff = (const float*)d_in[4];
    const float* boff = (const float*)d_in[5];
    const float* soff = (const float*)d_in[6];
    const float* Ww   = (const float*)d_in[7];
    const float* bw   = (const float*)d_in[8];
    const float* Wl   = (const float*)d_in[9];
    const float* bl   = (const float*)d_in[10];
    const float* lng  = (const float*)d_in[11];
    const float* lnb  = (const float*)d_in[12];

    transpose_kernel<<<dim3(960, 2), dim3(32, 8)>>>(img);
    bev_kernel<<<2048, 256>>>(velo, intr, bev, Woff, boff, soff,
                              Ww, bw, Wl, bl, lng, lnb, (float*)d_out);
}

// round 5
// speedup vs baseline: 1.1243x; 1.1243x over previous
#include <cuda_runtime.h>
#include <cuda_bf16.h>

#define EDIM 64
#define FHh 96
#define FWw 320
#define NPIX (FHh*FWw)

// img_feat transposed to [pixel][channel] (channel-contiguous, 256B per pixel)
__device__ float g_imgT[NPIX * EDIM];

typedef unsigned long long ull;

static __device__ __forceinline__ ull pk2(float x, float y) {
    ull r; asm("mov.b64 %0,{%1,%2};" : "=l"(r) : "f"(x), "f"(y)); return r;
}
static __device__ __forceinline__ float2 upk2(ull v) {
    float2 r; asm("mov.b64 {%0,%1},%2;" : "=f"(r.x), "=f"(r.y) : "l"(v)); return r;
}
static __device__ __forceinline__ void fma2(ull &d, ull a, ull b) {
    asm("fma.rn.f32x2 %0,%1,%2,%0;" : "+l"(d) : "l"(a), "l"(b));
}

// ------------------- transpose img_feat (E, H*W) -> (H*W, E) -------------------
__global__ void transpose_kernel(const float* __restrict__ src) {
    __shared__ float t[32][33];
    int p0 = blockIdx.x * 32;
    int e0 = blockIdx.y * 32;
    int tx = threadIdx.x, ty = threadIdx.y;  // (32, 8)
    #pragma unroll
    for (int r = 0; r < 32; r += 8)
        t[ty + r][tx] = src[(size_t)(e0 + ty + r) * NPIX + p0 + tx];
    __syncthreads();
    #pragma unroll
    for (int r = 0; r < 32; r += 8)
        g_imgT[(size_t)(p0 + ty + r) * EDIM + e0 + tx] = t[tx][ty + r];
}

// ------ gather-phase corner: 8 lanes cover one pixel's 256B as 2 full lines ------
// lane holds channels e in [cc*4, cc*4+4) (A[0..1]) and [32+cc*4, 32+cc*4+4) (A[2..3])
static __device__ __forceinline__ void gather8(int cx, int cy, float wgt,
                                               ull A[4], int cc) {
    if ((unsigned)cx < (unsigned)FWw && (unsigned)cy < (unsigned)FHh) {
        const float* p = &g_imgT[(size_t)(cy * FWw + cx) * EDIM];
        ulonglong2 qlo = *(const ulonglong2*)(p + cc * 4);        // line 0
        ulonglong2 qhi = *(const ulonglong2*)(p + 32 + cc * 4);   // line 1
        ull w2 = pk2(wgt, wgt);
        fma2(A[0], w2, qlo.x); fma2(A[1], w2, qlo.y);
        fma2(A[2], w2, qhi.x); fma2(A[3], w2, qhi.y);
    }
}

// ------------------- main fused kernel -------------------
// Resident mapping: warp = one z-column (8 voxels). lane = v*4 + c.
// Gather phase remaps to (v' = lane/8, cc = lane%8) over 2 rounds for
// full-line coalescing, then redistributes via per-warp smem staging.
__global__ __launch_bounds__(256) void bev_kernel(
    const float* __restrict__ velo,  const float* __restrict__ intr,
    const float* __restrict__ bev_emb,
    const float* __restrict__ Woff,  const float* __restrict__ boff,
    const float* __restrict__ soff,  const float* __restrict__ Ww,
    const float* __restrict__ bw,    const float* __restrict__ Wl,
    const float* __restrict__ bl,    const float* __restrict__ lng,
    const float* __restrict__ lnb,   float* __restrict__ out)
{
    __shared__ float s_wl[64 * 80];
    __shared__ float s_w9[64 * 12 + 24];
    __shared__ float s_bo[8], s_bw[4], s_bl[64], s_g[64], s_b[64];
    __shared__ float s_obuf[512];
    // staging: per warp 8 rows x 17 units x 16B = 2176B
    __shared__ __align__(16) float s_stage[8 * 544];

    int tid  = threadIdx.x;
    int w    = tid >> 5, lane = tid & 31;
    int v    = lane >> 2, c = lane & 3;
    int y    = blockIdx.x >> 4;
    int xg   = blockIdx.x & 15;
    int x    = xg * 8 + w;

    float T[12];
    #pragma unroll
    for (int r = 0; r < 3; r++)
        #pragma unroll
        for (int cq = 0; cq < 4; cq++)
            T[r*4+cq] = intr[r*3+0]*velo[0*4+cq] + intr[r*3+1]*velo[1*4+cq]
                      + intr[r*3+2]*velo[2*4+cq];

    float hx = 0.8f * (float)x;
    float hy = 51.2f - 0.8f * (float)y;
    float hz = 0.5f * (float)v - 2.5f;
    float p0 = T[0]*hx + T[1]*hy + T[2]*hz  + T[3];
    float p1 = T[4]*hx + T[5]*hy + T[6]*hz  + T[7];
    float p2 = T[8]*hx + T[9]*hy + T[10]*hz + T[11];
    float coordx = (p0 / p2) * (1.0f/640.0f) - 1.0f;
    float coordy = (p1 / p2) * (1.0f/192.0f) - 1.0f;

    int vox = x * 1024 + y * 8 + v;
    float bv[16];
    {
        const float4* bp = (const float4*)(bev_emb + (size_t)vox * 64 + c * 16);
        #pragma unroll
        for (int r = 0; r < 4; r++) {
            float4 q = bp[r];
            bv[4*r] = q.x; bv[4*r+1] = q.y; bv[4*r+2] = q.z; bv[4*r+3] = q.w;
        }
    }

    for (int it = 0; it < 3; ++it) {
        __syncthreads();
        // ---- cooperative weight staging ----
        for (int idx = tid; idx < 4096; idx += 256) {
            int e = idx >> 6, j = idx & 63;
            s_wl[e * 80 + (j >> 4) * 20 + (j & 15)] = Wl[it * 4096 + idx];
        }
        float sc = soff[it];
        for (int idx = tid; idx < 768; idx += 256) {
            int e = idx / 12, j = idx - e * 12;
            float val = 0.f;
            if (j < 6)       val = Woff[it * 384 + e * 6 + j];
            else if (j < 9)  val = Ww[it * 192 + e * 3 + (j - 6)];
            s_w9[e * 12 + (e >> 4) * 8 + j] = val;
        }
        if (tid < 6)                    s_bo[tid]      = boff[it*6 + tid] * sc;
        if (tid >= 32  && tid < 35)     s_bw[tid-32]   = bw[it*3 + tid-32];
        if (tid >= 64  && tid < 128)    s_bl[tid-64]   = bl[it*64 + tid-64];
        if (tid >= 128 && tid < 192)    s_g[tid-128]   = lng[it*64 + tid-128];
        if (tid >= 192)                 s_b[tid-192]   = lnb[it*64 + tid-192];
        __syncthreads();

        // ---- 9-output GEMV (offsets + attention logits) ----
        ull a0 = 0, a1 = 0, a2 = 0, a3 = 0; float a8 = 0.f;
        #pragma unroll
        for (int i = 0; i < 16; i++) {
            int e = c * 16 + i;
            float be = bv[i];
            ull be2 = pk2(be, be);
            const float* row = &s_w9[e * 12 + (e >> 4) * 8];
            ulonglong2 q0 = *(const ulonglong2*)row;
            ulonglong2 q1 = *(const ulonglong2*)(row + 4);
            fma2(a0, be2, q0.x); fma2(a1, be2, q0.y);
            fma2(a2, be2, q1.x); fma2(a3, be2, q1.y);
            a8 = fmaf(be, row[8], a8);
        }
        float d[9];
        { float2 t0 = upk2(a0); d[0]=t0.x; d[1]=t0.y;
          float2 t1 = upk2(a1); d[2]=t1.x; d[3]=t1.y;
          float2 t2 = upk2(a2); d[4]=t2.x; d[5]=t2.y;
          float2 t3 = upk2(a3); d[6]=t3.x; d[7]=t3.y; d[8]=a8; }
        #pragma unroll
        for (int s = 1; s <= 2; s <<= 1)
            #pragma unroll
            for (int t = 0; t < 9; t++)
                d[t] += __shfl_xor_sync(0xffffffffu, d[t], s);

        // ---- softmax over K=3 ----
        float l0 = d[6] + s_bw[0], l1 = d[7] + s_bw[1], l2 = d[8] + s_bw[2];
        float m  = fmaxf(l0, fmaxf(l1, l2));
        float e0 = __expf(l0 - m), e1 = __expf(l1 - m), e2 = __expf(l2 - m);
        float inv = 1.0f / (e0 + e1 + e2);

        // per-voxel continuous pixel coords (quad-uniform)
        float fxk[3], fyk[3], wkk[3];
        wkk[0] = e0 * inv; wkk[1] = e1 * inv; wkk[2] = e2 * inv;
        #pragma unroll
        for (int k = 0; k < 3; k++) {
            float gx = coordx + d[2*k]   * sc + s_bo[2*k];
            float gy = coordy + d[2*k+1] * sc + s_bo[2*k+1];
            fxk[k] = fmaf(gx, 160.f, 159.5f);   // ((gx+1)*320 - 1)/2
            fyk[k] = fmaf(gy, 48.f,  47.5f);    // ((gy+1)*96  - 1)/2
        }

        // ---- gather rounds: (v' = lane/8, cc = lane%8), 4 voxels per round ----
        int cc = lane & 7;
        ull A[2][4];
        #pragma unroll
        for (int r = 0; r < 2; r++) {
            A[r][0] = A[r][1] = A[r][2] = A[r][3] = 0ull;
            int src = (((lane >> 3) + 4*r) << 2);   // lane v*4 of gathered voxel
            #pragma unroll
            for (int k = 0; k < 3; k++) {
                float fx = __shfl_sync(0xffffffffu, fxk[k], src);
                float fy = __shfl_sync(0xffffffffu, fyk[k], src);
                float wg = __shfl_sync(0xffffffffu, wkk[k], src);
                float x0f = floorf(fx), y0f = floorf(fy);
                int ix = (int)x0f, iy = (int)y0f;
                float wx1 = fx - x0f, wy1 = fy - y0f;
                float wx0 = 1.f - wx1, wy0 = 1.f - wy1;
                gather8(ix,   iy,   wx0*wy0*wg, A[r], cc);
                gather8(ix+1, iy,   wx1*wy0*wg, A[r], cc);
                gather8(ix,   iy+1, wx0*wy1*wg, A[r], cc);
                gather8(ix+1, iy+1, wx1*wy1*wg, A[r], cc);
            }
        }
        // ---- stage + redistribute to resident (v, c) layout ----
        float* stw = s_stage + w * 544;
        #pragma unroll
        for (int r = 0; r < 2; r++) {
            int vv = (lane >> 3) + 4*r;
            float2 lo0 = upk2(A[r][0]), lo1 = upk2(A[r][1]);
            float2 hi0 = upk2(A[r][2]), hi1 = upk2(A[r][3]);
            *(float4*)&stw[(vv*17 + cc)     * 4] = make_float4(lo0.x, lo0.y, lo1.x, lo1.y);
            *(float4*)&stw[(vv*17 + 8 + cc) * 4] = make_float4(hi0.x, hi0.y, hi1.x, hi1.y);
        }
        __syncwarp();
        #pragma unroll
        for (int j4 = 0; j4 < 4; j4++) {
            float4 gf = *(const float4*)&stw[(v*17 + c*4 + j4) * 4];
            bv[4*j4+0] += gf.x; bv[4*j4+1] += gf.y;
            bv[4*j4+2] += gf.z; bv[4*j4+3] += gf.w;
        }

        // ---- 64x64 matmul: h = bev @ W_l + b_l ----
        ull acc[8];
        #pragma unroll
        for (int r = 0; r < 8; r++)
            acc[r] = pk2(s_bl[c*16 + 2*r], s_bl[c*16 + 2*r + 1]);
        #pragma unroll
        for (int g = 0; g < 4; ++g) {
            int src = (lane & ~3) | g;
            float ch[16];
            #pragma unroll
            for (int i = 0; i < 16; i++)
                ch[i] = __shfl_sync(0xffffffffu, bv[i], src);
            #pragma unroll
            for (int i = 0; i < 16; i++) {
                ull be2 = pk2(ch[i], ch[i]);
                const ulonglong2* wr =
                    (const ulonglong2*)&s_wl[(g*16 + i) * 80 + c * 20];
                ulonglong2 q0 = wr[0], q1 = wr[1], q2 = wr[2], q3 = wr[3];
                fma2(acc[0], be2, q0.x); fma2(acc[1], be2, q0.y);
                fma2(acc[2], be2, q1.x); fma2(acc[3], be2, q1.y);
                fma2(acc[4], be2, q2.x); fma2(acc[5], be2, q2.y);
                fma2(acc[6], be2, q3.x); fma2(acc[7], be2, q3.y);
            }
        }

        // ---- LayerNorm + residual ----
        float h[16];
        #pragma unroll
        for (int r = 0; r < 8; r++) {
            float2 t = upk2(acc[r]); h[2*r] = t.x; h[2*r+1] = t.y;
        }
        float s1 = 0.f, s2 = 0.f;
        #pragma unroll
        for (int i = 0; i < 16; i++) { s1 += h[i]; s2 += h[i]*h[i]; }
        #pragma unroll
        for (int s = 1; s <= 2; s <<= 1) {
            s1 += __shfl_xor_sync(0xffffffffu, s1, s);
            s2 += __shfl_xor_sync(0xffffffffu, s2, s);
        }
        float mu  = s1 * (1.f/64.f);
        float var = s2 * (1.f/64.f) - mu * mu;
        float rs  = rsqrtf(var + 1e-5f);
        #pragma unroll
        for (int i = 0; i < 16; i++)
            bv[i] += (h[i] - mu) * rs * s_g[c*16 + i] + s_b[c*16 + i];
    }

    // ---- mean over z + coalesced store ----
    #pragma unroll
    for (int i = 0; i < 16; i++) {
        float s = bv[i];
        s += __shfl_xor_sync(0xffffffffu, s, 4);
        s += __shfl_xor_sync(0xffffffffu, s, 8);
        s += __shfl_xor_sync(0xffffffffu, s, 16);
        bv[i] = s;
    }
    if (v == 0) {
        #pragma unroll
        for (int i = 0; i < 16; i++)
            s_obuf[(c*16 + i) * 8 + w] = bv[i] * 0.125f;
    }
    __syncthreads();
    for (int idx = tid; idx < 512; idx += 256) {
        int e = idx >> 3, xi = idx & 7;
        out[(size_t)e * 16384 + y * 128 + xg * 8 + xi] = s_obuf[idx];
    }
}

extern "C" void kernel_launch(void* const* d_in, const int* in_sizes, int n_in,
                              void* d_out, int out_size) {
    const float* velo = (const float*)d_in[0];
    const float* intr = (const float*)d_in[1];
    const float* img  = (const float*)d_in[2];
    const float* bev  = (const float*)d_in[3];
    const float* Woff = (const float*)d_in[4];
    const float* boff = (const float*)d_in[5];
    const float* soff = (const float*)d_in[6];
    const float* Ww   = (const float*)d_in[7];
    const float* bw   = (const float*)d_in[8];
    const float* Wl   = (const float*)d_in[9];
    const float* bl   = (const float*)d_in[10];
    const float* lng  = (const float*)d_in[11];
    const float* lnb  = (const float*)d_in[12];

    transpose_kernel<<<dim3(960, 2), dim3(32, 8)>>>(img);
    bev_kernel<<<2048, 256>>>(velo, intr, bev, Woff, boff, soff,
                              Ww, bw, Wl, bl, lng, lnb, (float*)d_out);
}

// round 8
// speedup vs baseline: 2.1052x; 1.8724x over previous
#include <cuda_runtime.h>
#include <cuda_bf16.h>

#define FHh 96
#define FWw 320
#define NPIX (FHh*FWw)

__device__ float g_imgT[NPIX * 64];

typedef unsigned long long ull;

static __device__ __forceinline__ ull pk2(float x, float y) {
    ull r; asm("mov.b64 %0,{%1,%2};" : "=l"(r) : "f"(x), "f"(y)); return r;
}
static __device__ __forceinline__ float2 upk2(ull v) {
    float2 r; asm("mov.b64 {%0,%1},%2;" : "=f"(r.x), "=f"(r.y) : "l"(v)); return r;
}
static __device__ __forceinline__ void fma2(ull &d, ull a, ull b) {
    asm("fma.rn.f32x2 %0,%1,%2,%0;" : "+l"(d) : "l"(a), "l"(b));
}
// pack: low half <- lo, high half <- hi
static __device__ __forceinline__ unsigned pkbf(float lo, float hi) {
    unsigned r; asm("cvt.rn.bf16x2.f32 %0, %1, %2;" : "=r"(r) : "f"(hi), "f"(lo)); return r;
}
static __device__ __forceinline__ void mma16816(float &d0, float &d1, float &d2, float &d3,
                                                unsigned a0, unsigned a2,
                                                unsigned b0, unsigned b1) {
    asm volatile("mma.sync.aligned.m16n8k16.row.col.f32.bf16.bf16.f32 "
                 "{%0,%1,%2,%3},{%4,%5,%6,%7},{%8,%9},{%0,%1,%2,%3};"
                 : "+f"(d0), "+f"(d1), "+f"(d2), "+f"(d3)
                 : "r"(a0), "r"(0u), "r"(a2), "r"(0u), "r"(b0), "r"(b1));
}
static __device__ __forceinline__ float bfr(float x) {  // bf16 round-trip
    return __bfloat162float(__float2bfloat16(x));
}

__global__ void transpose_kernel(const float* __restrict__ src) {
    __shared__ float t[32][33];
    int p0 = blockIdx.x * 32, e0 = blockIdx.y * 32;
    int tx = threadIdx.x, ty = threadIdx.y;
    #pragma unroll
    for (int r = 0; r < 32; r += 8)
        t[ty + r][tx] = src[(size_t)(e0 + ty + r) * NPIX + p0 + tx];
    __syncthreads();
    #pragma unroll
    for (int r = 0; r < 32; r += 8)
        g_imgT[(size_t)(p0 + ty + r) * 64 + e0 + tx] = t[tx][ty + r];
}

static __device__ __forceinline__ void gather8(int cx, int cy, float wgt,
                                               ull A[4], int cc) {
    if ((unsigned)cx < (unsigned)FWw && (unsigned)cy < (unsigned)FHh) {
        const float* p = &g_imgT[(size_t)(cy * FWw + cx) * 64];
        ulonglong2 qlo = *(const ulonglong2*)(p + cc * 4);
        ulonglong2 qhi = *(const ulonglong2*)(p + 32 + cc * 4);
        ull w2 = pk2(wgt, wgt);
        fma2(A[0], w2, qlo.x); fma2(A[1], w2, qlo.y);
        fma2(A[2], w2, qhi.x); fma2(A[3], w2, qhi.y);
    }
}

// Resident: warp = z-column (8 voxels), lane = v*4+c.
// PERMUTED channels: bv[4m+{0,1,2,3}] = ch {16m+2c, +1, 16m+8+2c, +1}.
__global__ __launch_bounds__(256) void bev_kernel(
    const float* __restrict__ velo,  const float* __restrict__ intr,
    const float* __restrict__ bev_emb,
    const float* __restrict__ Woff,  const float* __restrict__ boff,
    const float* __restrict__ soff,  const float* __restrict__ Ww,
    const float* __restrict__ bw,    const float* __restrict__ Wl,
    const float* __restrict__ bl,    const float* __restrict__ lng,
    const float* __restrict__ lnb,   float* __restrict__ out)
{
    __shared__ unsigned s_Bh[32 * 72];   // W pairs (e,e+1) bf16x2 hi, row e/2
    __shared__ unsigned s_Bl[32 * 72];   // lo residuals
    __shared__ __align__(16) float s_stage[8 * 576];  // per-warp, 8 rows x 72
    __shared__ float s_w9[768];
    __shared__ float s_bo[8], s_bw[4], s_bl[64], s_g[64], s_b[64];
    __shared__ float s_obuf[512];

    int tid  = threadIdx.x;
    int w    = tid >> 5, lane = tid & 31;
    int v    = lane >> 2, c = lane & 3;
    int y    = blockIdx.x >> 4;
    int xg   = blockIdx.x & 15;
    int x    = xg * 8 + w;

    float T[12];
    #pragma unroll
    for (int r = 0; r < 3; r++)
        #pragma unroll
        for (int q = 0; q < 4; q++)
            T[r*4+q] = intr[r*3+0]*velo[0*4+q] + intr[r*3+1]*velo[1*4+q]
                     + intr[r*3+2]*velo[2*4+q];

    float hx = 0.8f * (float)x;
    float hy = 51.2f - 0.8f * (float)y;
    float hz = 0.5f * (float)v - 2.5f;
    float p0 = T[0]*hx + T[1]*hy + T[2]*hz  + T[3];
    float p1 = T[4]*hx + T[5]*hy + T[6]*hz  + T[7];
    float p2 = T[8]*hx + T[9]*hy + T[10]*hz + T[11];
    float coordx = (p0 / p2) * (1.0f/640.0f) - 1.0f;
    float coordy = (p1 / p2) * (1.0f/192.0f) - 1.0f;

    int vox = x * 1024 + y * 8 + v;
    float bv[16];
    #pragma unroll
    for (int p = 0; p < 8; p++) {
        int e0 = 16*(p>>1) + 8*(p&1) + 2*c;
        float2 q = *(const float2*)(bev_emb + (size_t)vox * 64 + e0);
        bv[2*p] = q.x; bv[2*p+1] = q.y;
    }

    for (int it = 0; it < 3; ++it) {
        __syncthreads();
        // ---- B build: Wl -> bf16x2 e-pair tiles (hi/lo), rows e/2, stride 72 ----
        {
            int e2 = tid >> 3, j0 = (tid & 7) * 8;
            const float* r0 = Wl + it*4096 + (2*e2)*64 + j0;
            unsigned hbuf[8], lbuf[8];
            #pragma unroll
            for (int s4 = 0; s4 < 2; s4++) {
                float4 q0 = *(const float4*)(r0 + 4*s4);
                float4 q1 = *(const float4*)(r0 + 64 + 4*s4);
                float a[4] = {q0.x, q0.y, q0.z, q0.w};
                float b[4] = {q1.x, q1.y, q1.z, q1.w};
                #pragma unroll
                for (int s = 0; s < 4; s++) {
                    float h0 = bfr(a[s]), h1 = bfr(b[s]);
                    hbuf[4*s4+s] = pkbf(h0, h1);
                    lbuf[4*s4+s] = pkbf(a[s] - h0, b[s] - h1);
                }
            }
            #pragma unroll
            for (int s4 = 0; s4 < 2; s4++) {
                *(uint4*)&s_Bh[e2*72 + j0 + 4*s4] =
                    make_uint4(hbuf[4*s4], hbuf[4*s4+1], hbuf[4*s4+2], hbuf[4*s4+3]);
                *(uint4*)&s_Bl[e2*72 + j0 + 4*s4] =
                    make_uint4(lbuf[4*s4], lbuf[4*s4+1], lbuf[4*s4+2], lbuf[4*s4+3]);
            }
        }
        float sc = soff[it];
        for (int idx = tid; idx < 768; idx += 256) {
            int e = idx / 12, j = idx - e * 12;
            float val = 0.f;
            if (j < 6)       val = Woff[it * 384 + e * 6 + j];
            else if (j < 9)  val = Ww[it * 192 + e * 3 + (j - 6)];
            s_w9[e * 12 + j] = val;
        }
        if (tid < 6)                    s_bo[tid]    = boff[it*6 + tid] * sc;
        if (tid >= 32  && tid < 35)     s_bw[tid-32] = bw[it*3 + tid-32];
        if (tid >= 64  && tid < 128)    s_bl[tid-64] = bl[it*64 + tid-64];
        if (tid >= 128 && tid < 192)    s_g[tid-128] = lng[it*64 + tid-128];
        if (tid >= 192)                 s_b[tid-192] = lnb[it*64 + tid-192];
        __syncthreads();

        // ---- 9-output GEMV (permuted rows) ----
        ull a0 = 0, a1 = 0, a2 = 0, a3 = 0; float a8 = 0.f;
        #pragma unroll
        for (int i = 0; i < 16; i++) {
            int e = 16*(i>>2) + 8*((i>>1)&1) + 2*c + (i&1);
            float be = bv[i];
            ull be2 = pk2(be, be);
            const float* row = &s_w9[e * 12];
            ulonglong2 q0 = *(const ulonglong2*)row;
            ulonglong2 q1 = *(const ulonglong2*)(row + 4);
            fma2(a0, be2, q0.x); fma2(a1, be2, q0.y);
            fma2(a2, be2, q1.x); fma2(a3, be2, q1.y);
            a8 = fmaf(be, row[8], a8);
        }
        float d[9];
        { float2 t0 = upk2(a0); d[0]=t0.x; d[1]=t0.y;
          float2 t1 = upk2(a1); d[2]=t1.x; d[3]=t1.y;
          float2 t2 = upk2(a2); d[4]=t2.x; d[5]=t2.y;
          float2 t3 = upk2(a3); d[6]=t3.x; d[7]=t3.y; d[8]=a8; }
        #pragma unroll
        for (int s = 1; s <= 2; s <<= 1)
            #pragma unroll
            for (int t = 0; t < 9; t++)
                d[t] += __shfl_xor_sync(0xffffffffu, d[t], s);

        float l0 = d[6] + s_bw[0], l1 = d[7] + s_bw[1], l2 = d[8] + s_bw[2];
        float m  = fmaxf(l0, fmaxf(l1, l2));
        float e0 = __expf(l0 - m), e1 = __expf(l1 - m), e2 = __expf(l2 - m);
        float inv = 1.0f / (e0 + e1 + e2);

        float fxk[3], fyk[3], wkk[3];
        wkk[0] = e0 * inv; wkk[1] = e1 * inv; wkk[2] = e2 * inv;
        #pragma unroll
        for (int k = 0; k < 3; k++) {
            float gx = coordx + d[2*k]   * sc + s_bo[2*k];
            float gy = coordy + d[2*k+1] * sc + s_bo[2*k+1];
            fxk[k] = fmaf(gx, 160.f, 159.5f);
            fyk[k] = fmaf(gy, 48.f,  47.5f);
        }

        // ---- line-dense gather (2 rounds of 4 voxels) ----
        int cc = lane & 7;
        ull A[2][4];
        #pragma unroll
        for (int r = 0; r < 2; r++) {
            A[r][0] = A[r][1] = A[r][2] = A[r][3] = 0ull;
            int src = (((lane >> 3) + 4*r) << 2);
            #pragma unroll
            for (int k = 0; k < 3; k++) {
                float fx = __shfl_sync(0xffffffffu, fxk[k], src);
                float fy = __shfl_sync(0xffffffffu, fyk[k], src);
                float wg = __shfl_sync(0xffffffffu, wkk[k], src);
                float x0f = floorf(fx), y0f = floorf(fy);
                int ix = (int)x0f, iy = (int)y0f;
                float wx1 = fx - x0f, wy1 = fy - y0f;
                float wx0 = 1.f - wx1, wy0 = 1.f - wy1;
                gather8(ix,   iy,   wx0*wy0*wg, A[r], cc);
                gather8(ix+1, iy,   wx1*wy0*wg, A[r], cc);
                gather8(ix,   iy+1, wx0*wy1*wg, A[r], cc);
                gather8(ix+1, iy+1, wx1*wy1*wg, A[r], cc);
            }
        }
        // stage (natural channel order, stride 72) -> permuted readback
        float* stw = s_stage + w * 576;
        #pragma unroll
        for (int r = 0; r < 2; r++) {
            int vv = (lane >> 3) + 4*r;
            float2 lo0 = upk2(A[r][0]), lo1 = upk2(A[r][1]);
            float2 hi0 = upk2(A[r][2]), hi1 = upk2(A[r][3]);
            *(float4*)&stw[vv*72 + cc*4]      = make_float4(lo0.x, lo0.y, lo1.x, lo1.y);
            *(float4*)&stw[vv*72 + 32 + cc*4] = make_float4(hi0.x, hi0.y, hi1.x, hi1.y);
        }
        __syncwarp();
        #pragma unroll
        for (int p = 0; p < 8; p++) {
            int ep = 16*(p>>1) + 8*(p&1) + 2*c;
            float2 gf = *(const float2*)&stw[v*72 + ep];
            bv[2*p] += gf.x; bv[2*p+1] += gf.y;
        }

        // ==== mma.sync matmul: rows=voxels, A/D in resident registers ====
        unsigned ah0[4], ah2[4], al0[4], al2[4];
        #pragma unroll
        for (int mm = 0; mm < 4; mm++) {
            float x0 = bv[4*mm], x1 = bv[4*mm+1], x2 = bv[4*mm+2], x3 = bv[4*mm+3];
            float h0 = bfr(x0), h1 = bfr(x1), h2 = bfr(x2), h3 = bfr(x3);
            ah0[mm] = pkbf(h0, h1);       ah2[mm] = pkbf(h2, h3);
            al0[mm] = pkbf(x0-h0, x1-h1); al2[mm] = pkbf(x2-h2, x3-h3);
        }
        float hacc[16];
        #pragma unroll
        for (int n = 0; n < 8; n++) {
            float d0 = 0.f, d1 = 0.f, j2 = 0.f, j3 = 0.f;
            #pragma unroll
            for (int mm = 0; mm < 4; mm++) {
                unsigned bh0 = s_Bh[(8*mm + c)*72 + 8*n + v];
                unsigned bh1 = s_Bh[(8*mm + 4 + c)*72 + 8*n + v];
                unsigned bl0_ = s_Bl[(8*mm + c)*72 + 8*n + v];
                unsigned bl1_ = s_Bl[(8*mm + 4 + c)*72 + 8*n + v];
                mma16816(d0, d1, j2, j3, ah0[mm], ah2[mm], bh0, bh1);
                mma16816(d0, d1, j2, j3, al0[mm], al2[mm], bh0, bh1);
                mma16816(d0, d1, j2, j3, ah0[mm], ah2[mm], bl0_, bl1_);
            }
            hacc[2*n] = d0; hacc[2*n+1] = d1;
        }

        // ---- bias + LayerNorm + residual ----
        float h[16];
        #pragma unroll
        for (int p = 0; p < 8; p++) {
            int ep = 16*(p>>1) + 8*(p&1) + 2*c;
            float2 b2 = *(const float2*)&s_bl[ep];
            h[2*p] = hacc[2*p] + b2.x; h[2*p+1] = hacc[2*p+1] + b2.y;
        }
        float s1 = 0.f, s2 = 0.f;
        #pragma unroll
        for (int i = 0; i < 16; i++) { s1 += h[i]; s2 += h[i]*h[i]; }
        #pragma unroll
        for (int s = 1; s <= 2; s <<= 1) {
            s1 += __shfl_xor_sync(0xffffffffu, s1, s);
            s2 += __shfl_xor_sync(0xffffffffu, s2, s);
        }
        float mu  = s1 * (1.f/64.f);
        float var = s2 * (1.f/64.f) - mu * mu;
        float rs  = rsqrtf(var + 1e-5f);
        #pragma unroll
        for (int p = 0; p < 8; p++) {
            int ep = 16*(p>>1) + 8*(p&1) + 2*c;
            float2 g2 = *(const float2*)&s_g[ep];
            float2 b2 = *(const float2*)&s_b[ep];
            bv[2*p]   += (h[2*p]   - mu) * rs * g2.x + b2.x;
            bv[2*p+1] += (h[2*p+1] - mu) * rs * g2.y + b2.y;
        }
    }

    // ---- mean over z + store ----
    #pragma unroll
    for (int i = 0; i < 16; i++) {
        float s = bv[i];
        s += __shfl_xor_sync(0xffffffffu, s, 4);
        s += __shfl_xor_sync(0xffffffffu, s, 8);
        s += __shfl_xor_sync(0xffffffffu, s, 16);
        bv[i] = s;
    }
    if (v == 0) {
        #pragma unroll
        for (int i = 0; i < 16; i++) {
            int e = 16*(i>>2) + 8*((i>>1)&1) + 2*c + (i&1);
            s_obuf[e * 8 + w] = bv[i] * 0.125f;
        }
    }
    __syncthreads();
    for (int idx = tid; idx < 512; idx += 256) {
        int e = idx >> 3, xi = idx & 7;
        out[(size_t)e * 16384 + y * 128 + xg * 8 + xi] = s_obuf[idx];
    }
}

extern "C" void kernel_launch(void* const* d_in, const int* in_sizes, int n_in,
                              void* d_out, int out_size) {
    const float* velo = (const float*)d_in[0];
    const float* intr = (const float*)d_in[1];
    const float* img  = (const float*)d_in[2];
    const float* bev  = (const float*)d_in[3];
    const float* Woff = (const float*)d_in[4];
    const float* boff = (const float*)d_in[5];
    const float* soff = (const float*)d_in[6];
    const float* Ww   = (const float*)d_in[7];
    const float* bw   = (const float*)d_in[8];
    const float* Wl   = (const float*)d_in[9];
    const float* bl   = (const float*)d_in[10];
    const float* lng  = (const float*)d_in[11];
    const float* lnb  = (const float*)d_in[12];

    transpose_kernel<<<dim3(960, 2), dim3(32, 8)>>>(img);
    bev_kernel<<<2048, 256>>>(velo, intr, bev, Woff, boff, soff,
                              Ww, bw, Wl, bl, lng, lnb, (float*)d_out);
}

// round 9
// speedup vs baseline: 2.2940x; 1.0897x over previous
#include <cuda_runtime.h>
#include <cuda_bf16.h>

#define FHh 96
#define FWw 320
#define NPIX (FHh*FWw)

__device__ float g_imgT[NPIX * 64];
// precomputed bf16 hi/lo weight tiles (pair-packed), per iteration
__device__ unsigned g_Bh[3 * 2304];   // Wl pairs, rows e/2 (32) x stride 72
__device__ unsigned g_Bl[3 * 2304];
__device__ unsigned g_W9h[3 * 768];   // W9 pairs, rows e/2 (32) x stride 24
__device__ unsigned g_W9l[3 * 768];

typedef unsigned long long ull;

static __device__ __forceinline__ ull pk2(float x, float y) {
    ull r; asm("mov.b64 %0,{%1,%2};" : "=l"(r) : "f"(x), "f"(y)); return r;
}
static __device__ __forceinline__ float2 upk2(ull v) {
    float2 r; asm("mov.b64 {%0,%1},%2;" : "=f"(r.x), "=f"(r.y) : "l"(v)); return r;
}
static __device__ __forceinline__ void fma2(ull &d, ull a, ull b) {
    asm("fma.rn.f32x2 %0,%1,%2,%0;" : "+l"(d) : "l"(a), "l"(b));
}
// pack: low half <- lo, high half <- hi
static __device__ __forceinline__ unsigned pkbf(float lo, float hi) {
    unsigned r; asm("cvt.rn.bf16x2.f32 %0, %1, %2;" : "=r"(r) : "f"(hi), "f"(lo)); return r;
}
static __device__ __forceinline__ void mma16816(float &d0, float &d1, float &d2, float &d3,
                                                unsigned a0, unsigned a2,
                                                unsigned b0, unsigned b1) {
    asm volatile("mma.sync.aligned.m16n8k16.row.col.f32.bf16.bf16.f32 "
                 "{%0,%1,%2,%3},{%4,%5,%6,%7},{%8,%9},{%0,%1,%2,%3};"
                 : "+f"(d0), "+f"(d1), "+f"(d2), "+f"(d3)
                 : "r"(a0), "r"(0u), "r"(a2), "r"(0u), "r"(b0), "r"(b1));
}
static __device__ __forceinline__ float bfr(float x) {
    return __bfloat162float(__float2bfloat16(x));
}

// ------------------- prologue: transpose img_feat -------------------
__global__ void transpose_kernel(const float* __restrict__ src) {
    __shared__ float t[32][33];
    int p0 = blockIdx.x * 32, e0 = blockIdx.y * 32;
    int tx = threadIdx.x, ty = threadIdx.y;
    #pragma unroll
    for (int r = 0; r < 32; r += 8)
        t[ty + r][tx] = src[(size_t)(e0 + ty + r) * NPIX + p0 + tx];
    __syncthreads();
    #pragma unroll
    for (int r = 0; r < 32; r += 8)
        g_imgT[(size_t)(p0 + ty + r) * 64 + e0 + tx] = t[tx][ty + r];
}

// ------------------- prologue: build bf16 hi/lo weight tiles -------------------
__global__ void prep_kernel(const float* __restrict__ Wl,
                            const float* __restrict__ Woff,
                            const float* __restrict__ Ww) {
    int it = blockIdx.x, tid = threadIdx.x;
    // Wl pairs: word (e2, j) = bf16x2( Wl[2e2][j], Wl[2e2+1][j] )
    for (int idx = tid; idx < 2048; idx += 256) {
        int e2 = idx >> 6, j = idx & 63;
        float a = Wl[it*4096 + (2*e2)*64 + j];
        float b = Wl[it*4096 + (2*e2+1)*64 + j];
        float ha = bfr(a), hb = bfr(b);
        g_Bh[it*2304 + e2*72 + j] = pkbf(ha, hb);
        g_Bl[it*2304 + e2*72 + j] = pkbf(a - ha, b - hb);
    }
    // W9 pairs: 32 rows x 16 cols (j<6: Woff, j<9: Ww, else 0)
    for (int idx = tid; idx < 512; idx += 256) {
        int e2 = idx >> 4, j = idx & 15;
        float a = 0.f, b = 0.f;
        if (j < 6)      { a = Woff[it*384 + (2*e2)*6 + j];     b = Woff[it*384 + (2*e2+1)*6 + j]; }
        else if (j < 9) { a = Ww[it*192 + (2*e2)*3 + (j-6)];   b = Ww[it*192 + (2*e2+1)*3 + (j-6)]; }
        float ha = bfr(a), hb = bfr(b);
        g_W9h[it*768 + e2*24 + j] = pkbf(ha, hb);
        g_W9l[it*768 + e2*24 + j] = pkbf(a - ha, b - hb);
    }
}

static __device__ __forceinline__ void gather8(int cx, int cy, float wgt,
                                               ull A[4], int cc) {
    if ((unsigned)cx < (unsigned)FWw && (unsigned)cy < (unsigned)FHh) {
        const float* p = &g_imgT[(size_t)(cy * FWw + cx) * 64];
        ulonglong2 qlo = *(const ulonglong2*)(p + cc * 4);
        ulonglong2 qhi = *(const ulonglong2*)(p + 32 + cc * 4);
        ull w2 = pk2(wgt, wgt);
        fma2(A[0], w2, qlo.x); fma2(A[1], w2, qlo.y);
        fma2(A[2], w2, qhi.x); fma2(A[3], w2, qhi.y);
    }
}

// Resident: warp = z-column (8 voxels), lane = v*4+c.
// PERMUTED channels: bv[4m+{0,1,2,3}] = ch {16m+2c, +1, 16m+8+2c, +1}.
__global__ __launch_bounds__(256) void bev_kernel(
    const float* __restrict__ velo,  const float* __restrict__ intr,
    const float* __restrict__ bev_emb,
    const float* __restrict__ boff,  const float* __restrict__ soff,
    const float* __restrict__ bw,    const float* __restrict__ bl,
    const float* __restrict__ lng,   const float* __restrict__ lnb,
    float* __restrict__ out)
{
    __shared__ unsigned s_Bh[32 * 72];
    __shared__ unsigned s_Bl[32 * 72];
    __shared__ unsigned s_W9h[32 * 24];
    __shared__ unsigned s_W9l[32 * 24];
    __shared__ __align__(16) float s_stage[8 * 576];
    __shared__ float s_bo[8], s_bw[4], s_bl[64], s_g[64], s_b[64];
    __shared__ float s_obuf[512];

    int tid  = threadIdx.x;
    int w    = tid >> 5, lane = tid & 31;
    int v    = lane >> 2, c = lane & 3;
    int y    = blockIdx.x >> 4;
    int xg   = blockIdx.x & 15;
    int x    = xg * 8 + w;
    int qb   = lane & ~3;

    float T[12];
    #pragma unroll
    for (int r = 0; r < 3; r++)
        #pragma unroll
        for (int q = 0; q < 4; q++)
            T[r*4+q] = intr[r*3+0]*velo[0*4+q] + intr[r*3+1]*velo[1*4+q]
                     + intr[r*3+2]*velo[2*4+q];

    float hx = 0.8f * (float)x;
    float hy = 51.2f - 0.8f * (float)y;
    float hz = 0.5f * (float)v - 2.5f;
    float p0 = T[0]*hx + T[1]*hy + T[2]*hz  + T[3];
    float p1 = T[4]*hx + T[5]*hy + T[6]*hz  + T[7];
    float p2 = T[8]*hx + T[9]*hy + T[10]*hz + T[11];
    float coordx = (p0 / p2) * (1.0f/640.0f) - 1.0f;
    float coordy = (p1 / p2) * (1.0f/192.0f) - 1.0f;

    int vox = x * 1024 + y * 8 + v;
    float bv[16];
    #pragma unroll
    for (int p = 0; p < 8; p++) {
        int e0 = 16*(p>>1) + 8*(p&1) + 2*c;
        float2 q = *(const float2*)(bev_emb + (size_t)vox * 64 + e0);
        bv[2*p] = q.x; bv[2*p+1] = q.y;
    }

    for (int it = 0; it < 3; ++it) {
        __syncthreads();
        // ---- bulk-copy precomputed bf16 tiles ----
        {
            const uint4* gh = (const uint4*)(g_Bh + it*2304);
            const uint4* gl = (const uint4*)(g_Bl + it*2304);
            for (int i = tid; i < 576; i += 256) {
                ((uint4*)s_Bh)[i] = gh[i];
                ((uint4*)s_Bl)[i] = gl[i];
            }
            const uint4* g9h = (const uint4*)(g_W9h + it*768);
            const uint4* g9l = (const uint4*)(g_W9l + it*768);
            for (int i = tid; i < 192; i += 256) {
                ((uint4*)s_W9h)[i] = g9h[i];
                ((uint4*)s_W9l)[i] = g9l[i];
            }
        }
        float sc = soff[it];
        if (tid < 6)                    s_bo[tid]    = boff[it*6 + tid] * sc;
        if (tid >= 32  && tid < 35)     s_bw[tid-32] = bw[it*3 + tid-32];
        if (tid >= 64  && tid < 128)    s_bl[tid-64] = bl[it*64 + tid-64];
        if (tid >= 128 && tid < 192)    s_g[tid-128] = lng[it*64 + tid-128];
        if (tid >= 192)                 s_b[tid-192] = lnb[it*64 + tid-192];
        __syncthreads();

        // ---- pack pre-gather bv into bf16 hi/lo A fragments ----
        unsigned ah0[4], ah2[4], al0[4], al2[4];
        #pragma unroll
        for (int mm = 0; mm < 4; mm++) {
            float x0 = bv[4*mm], x1 = bv[4*mm+1], x2 = bv[4*mm+2], x3 = bv[4*mm+3];
            float h0 = bfr(x0), h1 = bfr(x1), h2 = bfr(x2), h3 = bfr(x3);
            ah0[mm] = pkbf(h0, h1);       ah2[mm] = pkbf(h2, h3);
            al0[mm] = pkbf(x0-h0, x1-h1); al2[mm] = pkbf(x2-h2, x3-h3);
        }

        // ---- 9-output GEMV via mma (n=0: cols 2c,2c+1; n=1: col 8 on c=0) ----
        float dd0 = 0.f, dd1 = 0.f, dd8 = 0.f, dd9 = 0.f;
        float z2 = 0.f, z3 = 0.f;
        #pragma unroll
        for (int mm = 0; mm < 4; mm++) {
            unsigned bh0 = s_W9h[(8*mm + c)*24 + v];
            unsigned bh1 = s_W9h[(8*mm + 4 + c)*24 + v];
            unsigned bl0_ = s_W9l[(8*mm + c)*24 + v];
            unsigned bl1_ = s_W9l[(8*mm + 4 + c)*24 + v];
            mma16816(dd0, dd1, z2, z3, ah0[mm], ah2[mm], bh0, bh1);
            mma16816(dd0, dd1, z2, z3, al0[mm], al2[mm], bh0, bh1);
            mma16816(dd0, dd1, z2, z3, ah0[mm], ah2[mm], bl0_, bl1_);
        }
        #pragma unroll
        for (int mm = 0; mm < 4; mm++) {
            unsigned bh0 = s_W9h[(8*mm + c)*24 + 8 + v];
            unsigned bh1 = s_W9h[(8*mm + 4 + c)*24 + 8 + v];
            unsigned bl0_ = s_W9l[(8*mm + c)*24 + 8 + v];
            unsigned bl1_ = s_W9l[(8*mm + 4 + c)*24 + 8 + v];
            mma16816(dd8, dd9, z2, z3, ah0[mm], ah2[mm], bh0, bh1);
            mma16816(dd8, dd9, z2, z3, al0[mm], al2[mm], bh0, bh1);
            mma16816(dd8, dd9, z2, z3, ah0[mm], ah2[mm], bl0_, bl1_);
        }
        // distribute 9 outputs across quad
        float d[9];
        #pragma unroll
        for (int t = 0; t < 4; t++) {
            d[2*t]   = __shfl_sync(0xffffffffu, dd0, qb | t);
            d[2*t+1] = __shfl_sync(0xffffffffu, dd1, qb | t);
        }
        d[8] = __shfl_sync(0xffffffffu, dd8, qb);

        // ---- softmax K=3 ----
        float l0 = d[6] + s_bw[0], l1 = d[7] + s_bw[1], l2 = d[8] + s_bw[2];
        float m  = fmaxf(l0, fmaxf(l1, l2));
        float e0 = __expf(l0 - m), e1 = __expf(l1 - m), e2 = __expf(l2 - m);
        float inv = 1.0f / (e0 + e1 + e2);

        float fxk[3], fyk[3], wkk[3];
        wkk[0] = e0 * inv; wkk[1] = e1 * inv; wkk[2] = e2 * inv;
        #pragma unroll
        for (int k = 0; k < 3; k++) {
            float gx = coordx + d[2*k]   * sc + s_bo[2*k];
            float gy = coordy + d[2*k+1] * sc + s_bo[2*k+1];
            fxk[k] = fmaf(gx, 160.f, 159.5f);
            fyk[k] = fmaf(gy, 48.f,  47.5f);
        }

        // ---- line-dense gather (2 rounds of 4 voxels) ----
        int cc = lane & 7;
        ull A[2][4];
        #pragma unroll
        for (int r = 0; r < 2; r++) {
            A[r][0] = A[r][1] = A[r][2] = A[r][3] = 0ull;
            int src = (((lane >> 3) + 4*r) << 2);
            #pragma unroll
            for (int k = 0; k < 3; k++) {
                float fx = __shfl_sync(0xffffffffu, fxk[k], src);
                float fy = __shfl_sync(0xffffffffu, fyk[k], src);
                float wg = __shfl_sync(0xffffffffu, wkk[k], src);
                float x0f = floorf(fx), y0f = floorf(fy);
                int ix = (int)x0f, iy = (int)y0f;
                float wx1 = fx - x0f, wy1 = fy - y0f;
                float wx0 = 1.f - wx1, wy0 = 1.f - wy1;
                gather8(ix,   iy,   wx0*wy0*wg, A[r], cc);
                gather8(ix+1, iy,   wx1*wy0*wg, A[r], cc);
                gather8(ix,   iy+1, wx0*wy1*wg, A[r], cc);
                gather8(ix+1, iy+1, wx1*wy1*wg, A[r], cc);
            }
        }
        // stage (natural channel order, stride 72) -> permuted readback
        float* stw = s_stage + w * 576;
        #pragma unroll
        for (int r = 0; r < 2; r++) {
            int vv = (lane >> 3) + 4*r;
            float2 lo0 = upk2(A[r][0]), lo1 = upk2(A[r][1]);
            float2 hi0 = upk2(A[r][2]), hi1 = upk2(A[r][3]);
            *(float4*)&stw[vv*72 + cc*4]      = make_float4(lo0.x, lo0.y, lo1.x, lo1.y);
            *(float4*)&stw[vv*72 + 32 + cc*4] = make_float4(hi0.x, hi0.y, hi1.x, hi1.y);
        }
        __syncwarp();
        #pragma unroll
        for (int p = 0; p < 8; p++) {
            int ep = 16*(p>>1) + 8*(p&1) + 2*c;
            float2 gf = *(const float2*)&stw[v*72 + ep];
            bv[2*p] += gf.x; bv[2*p+1] += gf.y;
        }

        // ==== main matmul via mma: rows=voxels, A/D in resident registers ====
        #pragma unroll
        for (int mm = 0; mm < 4; mm++) {
            float x0 = bv[4*mm], x1 = bv[4*mm+1], x2 = bv[4*mm+2], x3 = bv[4*mm+3];
            float h0 = bfr(x0), h1 = bfr(x1), h2 = bfr(x2), h3 = bfr(x3);
            ah0[mm] = pkbf(h0, h1);       ah2[mm] = pkbf(h2, h3);
            al0[mm] = pkbf(x0-h0, x1-h1); al2[mm] = pkbf(x2-h2, x3-h3);
        }
        float hacc[16];
        #pragma unroll
        for (int n = 0; n < 8; n++) {
            float d0 = 0.f, d1 = 0.f, j2 = 0.f, j3 = 0.f;
            #pragma unroll
            for (int mm = 0; mm < 4; mm++) {
                unsigned bh0 = s_Bh[(8*mm + c)*72 + 8*n + v];
                unsigned bh1 = s_Bh[(8*mm + 4 + c)*72 + 8*n + v];
                unsigned bl0_ = s_Bl[(8*mm + c)*72 + 8*n + v];
                unsigned bl1_ = s_Bl[(8*mm + 4 + c)*72 + 8*n + v];
                mma16816(d0, d1, j2, j3, ah0[mm], ah2[mm], bh0, bh1);
                mma16816(d0, d1, j2, j3, al0[mm], al2[mm], bh0, bh1);
                mma16816(d0, d1, j2, j3, ah0[mm], ah2[mm], bl0_, bl1_);
            }
            hacc[2*n] = d0; hacc[2*n+1] = d1;
        }

        // ---- bias + LayerNorm + residual ----
        float h[16];
        #pragma unroll
        for (int p = 0; p < 8; p++) {
            int ep = 16*(p>>1) + 8*(p&1) + 2*c;
            float2 b2 = *(const float2*)&s_bl[ep];
            h[2*p] = hacc[2*p] + b2.x; h[2*p+1] = hacc[2*p+1] + b2.y;
        }
        float s1 = 0.f, s2 = 0.f;
        #pragma unroll
        for (int i = 0; i < 16; i++) { s1 += h[i]; s2 += h[i]*h[i]; }
        #pragma unroll
        for (int s = 1; s <= 2; s <<= 1) {
            s1 += __shfl_xor_sync(0xffffffffu, s1, s);
            s2 += __shfl_xor_sync(0xffffffffu, s2, s);
        }
        float mu  = s1 * (1.f/64.f);
        float var = s2 * (1.f/64.f) - mu * mu;
        float rs  = rsqrtf(var + 1e-5f);
        #pragma unroll
        for (int p = 0; p < 8; p++) {
            int ep = 16*(p>>1) + 8*(p&1) + 2*c;
            float2 g2 = *(const float2*)&s_g[ep];
            float2 b2 = *(const float2*)&s_b[ep];
            bv[2*p]   += (h[2*p]   - mu) * rs * g2.x + b2.x;
            bv[2*p+1] += (h[2*p+1] - mu) * rs * g2.y + b2.y;
        }
    }

    // ---- mean over z + store ----
    #pragma unroll
    for (int i = 0; i < 16; i++) {
        float s = bv[i];
        s += __shfl_xor_sync(0xffffffffu, s, 4);
        s += __shfl_xor_sync(0xffffffffu, s, 8);
        s += __shfl_xor_sync(0xffffffffu, s, 16);
        bv[i] = s;
    }
    if (v == 0) {
        #pragma unroll
        for (int i = 0; i < 16; i++) {
            int e = 16*(i>>2) + 8*((i>>1)&1) + 2*c + (i&1);
            s_obuf[e * 8 + w] = bv[i] * 0.125f;
        }
    }
    __syncthreads();
    for (int idx = tid; idx < 512; idx += 256) {
        int e = idx >> 3, xi = idx & 7;
        out[(size_t)e * 16384 + y * 128 + xg * 8 + xi] = s_obuf[idx];
    }
}

extern "C" void kernel_launch(void* const* d_in, const int* in_sizes, int n_in,
                              void* d_out, int out_size) {
    const float* velo = (const float*)d_in[0];
    const float* intr = (const float*)d_in[1];
    const float* img  = (const float*)d_in[2];
    const float* bev  = (const float*)d_in[3];
    const float* Woff = (const float*)d_in[4];
    const float* boff = (const float*)d_in[5];
    const float* soff = (const float*)d_in[6];
    const float* Ww   = (const float*)d_in[7];
    const float* bw   = (const float*)d_in[8];
    const float* Wl   = (const float*)d_in[9];
    const float* bl   = (const float*)d_in[10];
    const float* lng  = (const float*)d_in[11];
    const float* lnb  = (const float*)d_in[12];

    transpose_kernel<<<dim3(960, 2), dim3(32, 8)>>>(img);
    prep_kernel<<<3, 256>>>(Wl, Woff, Ww);
    bev_kernel<<<2048, 256>>>(velo, intr, bev, boff, soff,
                              bw, bl, lng, lnb, (float*)d_out);
}

// round 10
// speedup vs baseline: 2.3913x; 1.0424x over previous
#include <cuda_runtime.h>
#include <cuda_bf16.h>

#define FHh 96
#define FWw 320
#define NPIX (FHh*FWw)

__device__ float g_imgT[NPIX * 64];
// precomputed bf16 hi/lo weight tiles (pair-packed), per iteration
__device__ unsigned g_Bh[3 * 2304];   // Wl pairs, rows e/2 (32) x stride 72
__device__ unsigned g_Bl[3 * 2304];
__device__ unsigned g_W9h[3 * 768];   // W9 pairs, rows e/2 (32) x stride 24
__device__ unsigned g_W9l[3 * 768];

typedef unsigned long long ull;

static __device__ __forceinline__ ull pk2(float x, float y) {
    ull r; asm("mov.b64 %0,{%1,%2};" : "=l"(r) : "f"(x), "f"(y)); return r;
}
static __device__ __forceinline__ float2 upk2(ull v) {
    float2 r; asm("mov.b64 {%0,%1},%2;" : "=f"(r.x), "=f"(r.y) : "l"(v)); return r;
}
static __device__ __forceinline__ void fma2(ull &d, ull a, ull b) {
    asm("fma.rn.f32x2 %0,%1,%2,%0;" : "+l"(d) : "l"(a), "l"(b));
}
// pack: low half <- lo, high half <- hi
static __device__ __forceinline__ unsigned pkbf(float lo, float hi) {
    unsigned r; asm("cvt.rn.bf16x2.f32 %0, %1, %2;" : "=r"(r) : "f"(hi), "f"(lo)); return r;
}
static __device__ __forceinline__ void mma16816(float &d0, float &d1, float &d2, float &d3,
                                                unsigned a0, unsigned a2,
                                                unsigned b0, unsigned b1) {
    asm volatile("mma.sync.aligned.m16n8k16.row.col.f32.bf16.bf16.f32 "
                 "{%0,%1,%2,%3},{%4,%5,%6,%7},{%8,%9},{%0,%1,%2,%3};"
                 : "+f"(d0), "+f"(d1), "+f"(d2), "+f"(d3)
                 : "r"(a0), "r"(0u), "r"(a2), "r"(0u), "r"(b0), "r"(b1));
}
static __device__ __forceinline__ float bfr(float x) {
    return __bfloat162float(__float2bfloat16(x));
}

// ------------------- prologue: transpose img_feat (full 64-ch rows) -----------
__global__ void transpose_kernel(const float* __restrict__ src) {
    __shared__ float t[64][33];
    int p0 = blockIdx.x * 32;
    int tx = threadIdx.x, ty = threadIdx.y;   // (32, 8)
    #pragma unroll
    for (int r = 0; r < 64; r += 8)
        t[ty + r][tx] = src[(size_t)(ty + r) * NPIX + p0 + tx];
    __syncthreads();
    int tid = ty * 32 + tx;
    #pragma unroll
    for (int i = 0; i < 8; i++) {
        int idx = tid + i * 256;           // pixel-local word index
        int px = idx >> 6, e = idx & 63;
        g_imgT[(size_t)(p0 + px) * 64 + e] = t[e][px];
    }
}

// ------------------- prologue: build bf16 hi/lo weight tiles -------------------
__global__ void prep_kernel(const float* __restrict__ Wl,
                            const float* __restrict__ Woff,
                            const float* __restrict__ Ww) {
    int it = blockIdx.x, tid = threadIdx.x;
    for (int idx = tid; idx < 2048; idx += 256) {
        int e2 = idx >> 6, j = idx & 63;
        float a = Wl[it*4096 + (2*e2)*64 + j];
        float b = Wl[it*4096 + (2*e2+1)*64 + j];
        float ha = bfr(a), hb = bfr(b);
        g_Bh[it*2304 + e2*72 + j] = pkbf(ha, hb);
        g_Bl[it*2304 + e2*72 + j] = pkbf(a - ha, b - hb);
    }
    for (int idx = tid; idx < 512; idx += 256) {
        int e2 = idx >> 4, j = idx & 15;
        float a = 0.f, b = 0.f;
        if (j < 6)      { a = Woff[it*384 + (2*e2)*6 + j];     b = Woff[it*384 + (2*e2+1)*6 + j]; }
        else if (j < 9) { a = Ww[it*192 + (2*e2)*3 + (j-6)];   b = Ww[it*192 + (2*e2+1)*3 + (j-6)]; }
        float ha = bfr(a), hb = bfr(b);
        g_W9h[it*768 + e2*24 + j] = pkbf(ha, hb);
        g_W9l[it*768 + e2*24 + j] = pkbf(a - ha, b - hb);
    }
}

static __device__ __forceinline__ void gather8(int cx, int cy, float wgt,
                                               ull A[4], int cc) {
    if ((unsigned)cx < (unsigned)FWw && (unsigned)cy < (unsigned)FHh) {
        const float* p = &g_imgT[(size_t)(cy * FWw + cx) * 64];
        ulonglong2 qlo = *(const ulonglong2*)(p + cc * 4);
        ulonglong2 qhi = *(const ulonglong2*)(p + 32 + cc * 4);
        ull w2 = pk2(wgt, wgt);
        fma2(A[0], w2, qlo.x); fma2(A[1], w2, qlo.y);
        fma2(A[2], w2, qhi.x); fma2(A[3], w2, qhi.y);
    }
}

// Resident: warp = z-column (8 voxels), lane = v*4+c.
// PERMUTED channels: bv[4m+{0,1,2,3}] = ch {16m+2c, +1, 16m+8+2c, +1}.
__global__ __launch_bounds__(256, 3) void bev_kernel(
    const float* __restrict__ velo,  const float* __restrict__ intr,
    const float* __restrict__ bev_emb,
    const float* __restrict__ boff,  const float* __restrict__ soff,
    const float* __restrict__ bw,    const float* __restrict__ bl,
    const float* __restrict__ lng,   const float* __restrict__ lnb,
    float* __restrict__ out)
{
    __shared__ unsigned s_Bh[32 * 72];
    __shared__ unsigned s_Bl[32 * 72];
    __shared__ unsigned s_W9h[32 * 24];
    __shared__ unsigned s_W9l[32 * 24];
    __shared__ __align__(16) float s_stage[8 * 576];
    __shared__ float s_bo[8], s_bw[4], s_bl[64], s_g[64], s_b[64];
    __shared__ float s_obuf[512];

    int tid  = threadIdx.x;
    int w    = tid >> 5, lane = tid & 31;
    int v    = lane >> 2, c = lane & 3;
    int y    = blockIdx.x >> 4;
    int xg   = blockIdx.x & 15;
    int x    = xg * 8 + w;
    int qb   = lane & ~3;

    float T[12];
    #pragma unroll
    for (int r = 0; r < 3; r++)
        #pragma unroll
        for (int q = 0; q < 4; q++)
            T[r*4+q] = intr[r*3+0]*velo[0*4+q] + intr[r*3+1]*velo[1*4+q]
                     + intr[r*3+2]*velo[2*4+q];

    float hx = 0.8f * (float)x;
    float hy = 51.2f - 0.8f * (float)y;
    float hz = 0.5f * (float)v - 2.5f;
    float p0 = T[0]*hx + T[1]*hy + T[2]*hz  + T[3];
    float p1 = T[4]*hx + T[5]*hy + T[6]*hz  + T[7];
    float p2 = T[8]*hx + T[9]*hy + T[10]*hz + T[11];
    float coordx = (p0 / p2) * (1.0f/640.0f) - 1.0f;
    float coordy = (p1 / p2) * (1.0f/192.0f) - 1.0f;

    int vox = x * 1024 + y * 8 + v;
    float bv[16];
    #pragma unroll
    for (int p = 0; p < 8; p++) {
        int e0 = 16*(p>>1) + 8*(p&1) + 2*c;
        float2 q = *(const float2*)(bev_emb + (size_t)vox * 64 + e0);
        bv[2*p] = q.x; bv[2*p+1] = q.y;
    }

    for (int it = 0; it < 3; ++it) {
        __syncthreads();
        // ---- bulk-copy precomputed bf16 tiles ----
        {
            const uint4* gh = (const uint4*)(g_Bh + it*2304);
            const uint4* gl = (const uint4*)(g_Bl + it*2304);
            for (int i = tid; i < 576; i += 256) {
                ((uint4*)s_Bh)[i] = gh[i];
                ((uint4*)s_Bl)[i] = gl[i];
            }
            const uint4* g9h = (const uint4*)(g_W9h + it*768);
            const uint4* g9l = (const uint4*)(g_W9l + it*768);
            for (int i = tid; i < 192; i += 256) {
                ((uint4*)s_W9h)[i] = g9h[i];
                ((uint4*)s_W9l)[i] = g9l[i];
            }
        }
        float sc = soff[it];
        if (tid < 6)                    s_bo[tid]    = boff[it*6 + tid] * sc;
        if (tid >= 32  && tid < 35)     s_bw[tid-32] = bw[it*3 + tid-32];
        if (tid >= 64  && tid < 128)    s_bl[tid-64] = bl[it*64 + tid-64];
        if (tid >= 128 && tid < 192)    s_g[tid-128] = lng[it*64 + tid-128];
        if (tid >= 192)                 s_b[tid-192] = lnb[it*64 + tid-192];
        __syncthreads();

        // ---- pack pre-gather bv into bf16 hi/lo A fragments ----
        unsigned ah0[4], ah2[4], al0[4], al2[4];
        #pragma unroll
        for (int mm = 0; mm < 4; mm++) {
            float x0 = bv[4*mm], x1 = bv[4*mm+1], x2 = bv[4*mm+2], x3 = bv[4*mm+3];
            float h0 = bfr(x0), h1 = bfr(x1), h2 = bfr(x2), h3 = bfr(x3);
            ah0[mm] = pkbf(h0, h1);       ah2[mm] = pkbf(h2, h3);
            al0[mm] = pkbf(x0-h0, x1-h1); al2[mm] = pkbf(x2-h2, x3-h3);
        }

        // ---- 9-output GEMV via mma ----
        float dd0 = 0.f, dd1 = 0.f, dd8 = 0.f, dd9 = 0.f;
        float z2 = 0.f, z3 = 0.f;
        #pragma unroll
        for (int mm = 0; mm < 4; mm++) {
            unsigned bh0 = s_W9h[(8*mm + c)*24 + v];
            unsigned bh1 = s_W9h[(8*mm + 4 + c)*24 + v];
            unsigned bl0_ = s_W9l[(8*mm + c)*24 + v];
            unsigned bl1_ = s_W9l[(8*mm + 4 + c)*24 + v];
            mma16816(dd0, dd1, z2, z3, ah0[mm], ah2[mm], bh0, bh1);
            mma16816(dd0, dd1, z2, z3, al0[mm], al2[mm], bh0, bh1);
            mma16816(dd0, dd1, z2, z3, ah0[mm], ah2[mm], bl0_, bl1_);
        }
        #pragma unroll
        for (int mm = 0; mm < 4; mm++) {
            unsigned bh0 = s_W9h[(8*mm + c)*24 + 8 + v];
            unsigned bh1 = s_W9h[(8*mm + 4 + c)*24 + 8 + v];
            unsigned bl0_ = s_W9l[(8*mm + c)*24 + 8 + v];
            unsigned bl1_ = s_W9l[(8*mm + 4 + c)*24 + 8 + v];
            mma16816(dd8, dd9, z2, z3, ah0[mm], ah2[mm], bh0, bh1);
            mma16816(dd8, dd9, z2, z3, al0[mm], al2[mm], bh0, bh1);
            mma16816(dd8, dd9, z2, z3, ah0[mm], ah2[mm], bl0_, bl1_);
        }
        float d[9];
        #pragma unroll
        for (int t = 0; t < 4; t++) {
            d[2*t]   = __shfl_sync(0xffffffffu, dd0, qb | t);
            d[2*t+1] = __shfl_sync(0xffffffffu, dd1, qb | t);
        }
        d[8] = __shfl_sync(0xffffffffu, dd8, qb);

        // ---- softmax K=3 ----
        float l0 = d[6] + s_bw[0], l1 = d[7] + s_bw[1], l2 = d[8] + s_bw[2];
        float m  = fmaxf(l0, fmaxf(l1, l2));
        float e0 = __expf(l0 - m), e1 = __expf(l1 - m), e2 = __expf(l2 - m);
        float inv = 1.0f / (e0 + e1 + e2);

        float fxk[3], fyk[3], wkk[3];
        wkk[0] = e0 * inv; wkk[1] = e1 * inv; wkk[2] = e2 * inv;
        #pragma unroll
        for (int k = 0; k < 3; k++) {
            float gx = coordx + d[2*k]   * sc + s_bo[2*k];
            float gy = coordy + d[2*k+1] * sc + s_bo[2*k+1];
            fxk[k] = fmaf(gx, 160.f, 159.5f);
            fyk[k] = fmaf(gy, 48.f,  47.5f);
        }

        // ---- line-dense gather (2 rounds of 4 voxels) ----
        int cc = lane & 7;
        ull A[2][4];
        #pragma unroll
        for (int r = 0; r < 2; r++) {
            A[r][0] = A[r][1] = A[r][2] = A[r][3] = 0ull;
            int src = (((lane >> 3) + 4*r) << 2);
            #pragma unroll
            for (int k = 0; k < 3; k++) {
                float fx = __shfl_sync(0xffffffffu, fxk[k], src);
                float fy = __shfl_sync(0xffffffffu, fyk[k], src);
                float wg = __shfl_sync(0xffffffffu, wkk[k], src);
                float x0f = floorf(fx), y0f = floorf(fy);
                int ix = (int)x0f, iy = (int)y0f;
                float wx1 = fx - x0f, wy1 = fy - y0f;
                float wx0 = 1.f - wx1, wy0 = 1.f - wy1;
                gather8(ix,   iy,   wx0*wy0*wg, A[r], cc);
                gather8(ix+1, iy,   wx1*wy0*wg, A[r], cc);
                gather8(ix,   iy+1, wx0*wy1*wg, A[r], cc);
                gather8(ix+1, iy+1, wx1*wy1*wg, A[r], cc);
            }
        }
        // stage (natural channel order, stride 72) -> permuted readback
        float* stw = s_stage + w * 576;
        #pragma unroll
        for (int r = 0; r < 2; r++) {
            int vv = (lane >> 3) + 4*r;
            float2 lo0 = upk2(A[r][0]), lo1 = upk2(A[r][1]);
            float2 hi0 = upk2(A[r][2]), hi1 = upk2(A[r][3]);
            *(float4*)&stw[vv*72 + cc*4]      = make_float4(lo0.x, lo0.y, lo1.x, lo1.y);
            *(float4*)&stw[vv*72 + 32 + cc*4] = make_float4(hi0.x, hi0.y, hi1.x, hi1.y);
        }
        __syncwarp();
        #pragma unroll
        for (int p = 0; p < 8; p++) {
            int ep = 16*(p>>1) + 8*(p&1) + 2*c;
            float2 gf = *(const float2*)&stw[v*72 + ep];
            bv[2*p] += gf.x; bv[2*p+1] += gf.y;
        }

        // ==== main matmul via mma: rows=voxels, A/D in resident registers ====
        #pragma unroll
        for (int mm = 0; mm < 4; mm++) {
            float x0 = bv[4*mm], x1 = bv[4*mm+1], x2 = bv[4*mm+2], x3 = bv[4*mm+3];
            float h0 = bfr(x0), h1 = bfr(x1), h2 = bfr(x2), h3 = bfr(x3);
            ah0[mm] = pkbf(h0, h1);       ah2[mm] = pkbf(h2, h3);
            al0[mm] = pkbf(x0-h0, x1-h1); al2[mm] = pkbf(x2-h2, x3-h3);
        }
        float hacc[16];
        #pragma unroll
        for (int n = 0; n < 8; n++) {
            float d0 = 0.f, d1 = 0.f, j2 = 0.f, j3 = 0.f;
            #pragma unroll
            for (int mm = 0; mm < 4; mm++) {
                unsigned bh0 = s_Bh[(8*mm + c)*72 + 8*n + v];
                unsigned bh1 = s_Bh[(8*mm + 4 + c)*72 + 8*n + v];
                unsigned bl0_ = s_Bl[(8*mm + c)*72 + 8*n + v];
                unsigned bl1_ = s_Bl[(8*mm + 4 + c)*72 + 8*n + v];
                mma16816(d0, d1, j2, j3, ah0[mm], ah2[mm], bh0, bh1);
                mma16816(d0, d1, j2, j3, al0[mm], al2[mm], bh0, bh1);
                mma16816(d0, d1, j2, j3, ah0[mm], ah2[mm], bl0_, bl1_);
            }
            hacc[2*n] = d0; hacc[2*n+1] = d1;
        }

        // ---- bias + LayerNorm + residual ----
        float h[16];
        #pragma unroll
        for (int p = 0; p < 8; p++) {
            int ep = 16*(p>>1) + 8*(p&1) + 2*c;
            float2 b2 = *(const float2*)&s_bl[ep];
            h[2*p] = hacc[2*p] + b2.x; h[2*p+1] = hacc[2*p+1] + b2.y;
        }
        float s1 = 0.f, s2 = 0.f;
        #pragma unroll
        for (int i = 0; i < 16; i++) { s1 += h[i]; s2 += h[i]*h[i]; }
        #pragma unroll
        for (int s = 1; s <= 2; s <<= 1) {
            s1 += __shfl_xor_sync(0xffffffffu, s1, s);
            s2 += __shfl_xor_sync(0xffffffffu, s2, s);
        }
        float mu  = s1 * (1.f/64.f);
        float var = s2 * (1.f/64.f) - mu * mu;
        float rs  = rsqrtf(var + 1e-5f);
        #pragma unroll
        for (int p = 0; p < 8; p++) {
            int ep = 16*(p>>1) + 8*(p&1) + 2*c;
            float2 g2 = *(const float2*)&s_g[ep];
            float2 b2 = *(const float2*)&s_b[ep];
            bv[2*p]   += (h[2*p]   - mu) * rs * g2.x + b2.x;
            bv[2*p+1] += (h[2*p+1] - mu) * rs * g2.y + b2.y;
        }
    }

    // ---- mean over z + store ----
    #pragma unroll
    for (int i = 0; i < 16; i++) {
        float s = bv[i];
        s += __shfl_xor_sync(0xffffffffu, s, 4);
        s += __shfl_xor_sync(0xffffffffu, s, 8);
        s += __shfl_xor_sync(0xffffffffu, s, 16);
        bv[i] = s;
    }
    if (v == 0) {
        #pragma unroll
        for (int i = 0; i < 16; i++) {
            int e = 16*(i>>2) + 8*((i>>1)&1) + 2*c + (i&1);
            s_obuf[e * 8 + w] = bv[i] * 0.125f;
        }
    }
    __syncthreads();
    for (int idx = tid; idx < 512; idx += 256) {
        int e = idx >> 3, xi = idx & 7;
        out[(size_t)e * 16384 + y * 128 + xg * 8 + xi] = s_obuf[idx];
    }
}

extern "C" void kernel_launch(void* const* d_in, const int* in_sizes, int n_in,
                              void* d_out, int out_size) {
    const float* velo = (const float*)d_in[0];
    const float* intr = (const float*)d_in[1];
    const float* img  = (const float*)d_in[2];
    const float* bev  = (const float*)d_in[3];
    const float* Woff = (const float*)d_in[4];
    const float* boff = (const float*)d_in[5];
    const float* soff = (const float*)d_in[6];
    const float* Ww   = (const float*)d_in[7];
    const float* bw   = (const float*)d_in[8];
    const float* Wl   = (const float*)d_in[9];
    const float* bl   = (const float*)d_in[10];
    const float* lng  = (const float*)d_in[11];
    const float* lnb  = (const float*)d_in[12];

    transpose_kernel<<<960, dim3(32, 8)>>>(img);
    prep_kernel<<<3, 256>>>(Wl, Woff, Ww);
    bev_kernel<<<2048, 256>>>(velo, intr, bev, boff, soff,
                              bw, bl, lng, lnb, (float*)d_out);
}